// round 2
// baseline (speedup 1.0000x reference)
#include <cuda_runtime.h>
#include <math.h>

#define NN   50000
#define NE   1600000
#define NTOT (NE + NN)
#define NG   512
#define NF   128
#define NH   4

// ---- scratch (device globals; no allocation allowed) ----
__device__ float g_h [(size_t)NN * NF];   // h = x @ W for current layer
__device__ float g_xa[(size_t)NN * NF];   // ping
__device__ float g_xb[(size_t)NN * NF];   // pong
__device__ float g_as[NN * NH];
__device__ float g_ad[NN * NH];
__device__ int   g_rowptr[NN + 1];
__device__ int   g_cursor[NN];
__device__ int   g_col[NTOT];
__device__ int   g_gstart[NG + 1];
__device__ int   g_ei64;    // 1 if edge_index delivered as int64, 0 if int32
__device__ int   g_bat64;   // same for batch

// ---------- runtime index-width detection (int64 vs int32 delivery) ----------
__global__ void k_detect(const void* __restrict__ ei, const void* __restrict__ bat) {
    if (threadIdx.x != 0 || blockIdx.x != 0) return;
    const unsigned long long* e = (const unsigned long long*)ei;
    int is64 = 1;
    for (int i = 0; i < 256; i++)            // int64: values < 2^31 -> hi word 0
        if (e[i] >> 31) { is64 = 0; break; } // int32: hi word = next index != 0
    g_ei64 = is64;
    const unsigned long long* b = (const unsigned long long*)bat;
    int b64 = 1;
    for (int i = 20000; i < 20256; i++)      // safe under both widths (i < NN/2)
        if (b[i] >> 31) { b64 = 0; break; }  // int32 pair hi ~ graph id ~400 != 0
    g_bat64 = b64;
}

__device__ __forceinline__ int load_idx(const void* p, int i, int is64) {
    return is64 ? (int)((const long long*)p)[i] : ((const int*)p)[i];
}

// ============================ CSR build ============================

__global__ void k_init_counts() {
    int i = blockIdx.x * blockDim.x + threadIdx.x;
    if (i < NN) g_cursor[i] = 1;   // 1 = self-loop
}

__global__ void k_hist(const void* __restrict__ ei) {
    int i = blockIdx.x * blockDim.x + threadIdx.x;
    if (i < NE) atomicAdd(&g_cursor[load_idx(ei, NE + i, g_ei64)], 1);
}

// single-block exclusive scan of counts -> rowptr; also reset cursor to rowptr
__global__ void k_scan() {
    __shared__ int sh[1024];
    const int CH = (NN + 1023) / 1024;   // 49
    int t = threadIdx.x;
    int beg = t * CH;
    int end = min(beg + CH, NN);
    int sum = 0;
    for (int i = beg; i < end; i++) sum += g_cursor[i];
    sh[t] = sum;
    __syncthreads();
    for (int off = 1; off < 1024; off <<= 1) {
        int v = (t >= off) ? sh[t - off] : 0;
        __syncthreads();
        sh[t] += v;
        __syncthreads();
    }
    int run = sh[t] - sum;   // exclusive prefix for this thread's chunk
    for (int i = beg; i < end; i++) {
        int c = g_cursor[i];
        g_rowptr[i] = run;
        g_cursor[i] = run;
        run += c;
    }
    if (t == 1023) g_rowptr[NN] = sh[1023];
}

__global__ void k_scatter(const void* __restrict__ ei) {
    int i = blockIdx.x * blockDim.x + threadIdx.x;
    if (i >= NTOT) return;
    int src, dst;
    if (i < NE) {
        int is64 = g_ei64;
        src = load_idx(ei, i, is64);
        dst = load_idx(ei, NE + i, is64);
    } else {
        src = dst = i - NE;   // self-loop
    }
    int p = atomicAdd(&g_cursor[dst], 1);
    g_col[p] = src;
}

__global__ void k_gstart(const void* __restrict__ batch) {
    int i = blockIdx.x * blockDim.x + threadIdx.x;
    if (i >= NN) return;
    int is64 = g_bat64;
    int b  = load_idx(batch, i, is64);
    int bp = (i == 0) ? -1 : load_idx(batch, i - 1, is64);
    for (int g = bp + 1; g <= b; g++) g_gstart[g] = i;
    if (i == NN - 1)
        for (int g = b + 1; g <= NG; g++) g_gstart[g] = NN;
}

// ============================ GEMM: g_h = X @ W ============================
// 128x128 tile per block, 256 threads, 8x8 microtile, K-chunks of 16.

__global__ __launch_bounds__(256) void k_gemm(const float* __restrict__ X,
                                              const float* __restrict__ W) {
    __shared__ __align__(16) float As[16][128];   // [k][row]
    __shared__ __align__(16) float Bs[16][128];   // [k][col]
    int tid  = threadIdx.x;
    int tx   = tid & 15, ty = tid >> 4;
    int row0 = blockIdx.x * 128;

    float acc[8][8];
#pragma unroll
    for (int i = 0; i < 8; i++)
#pragma unroll
        for (int j = 0; j < 8; j++) acc[i][j] = 0.f;

    for (int k0 = 0; k0 < 128; k0 += 16) {
#pragma unroll
        for (int l = 0; l < 2; l++) {
            int f4 = tid * 2 + l;
            // X tile: 128 rows x 16 k
            int r = f4 >> 2, kq = (f4 & 3) << 2;
            int gr = row0 + r;
            float4 v = make_float4(0.f, 0.f, 0.f, 0.f);
            if (gr < NN) v = *(const float4*)(X + (size_t)gr * NF + k0 + kq);
            As[kq + 0][r] = v.x; As[kq + 1][r] = v.y;
            As[kq + 2][r] = v.z; As[kq + 3][r] = v.w;
            // W tile: 16 k x 128 cols (row-major)
            int kr = f4 >> 5, nq = (f4 & 31) << 2;
            *(float4*)&Bs[kr][nq] = *(const float4*)(W + (size_t)(k0 + kr) * NF + nq);
        }
        __syncthreads();
#pragma unroll
        for (int kk = 0; kk < 16; kk++) {
            float a[8], b[8];
            *(float4*)&a[0] = *(const float4*)&As[kk][ty * 8];
            *(float4*)&a[4] = *(const float4*)&As[kk][ty * 8 + 4];
            *(float4*)&b[0] = *(const float4*)&Bs[kk][tx * 8];
            *(float4*)&b[4] = *(const float4*)&Bs[kk][tx * 8 + 4];
#pragma unroll
            for (int i = 0; i < 8; i++)
#pragma unroll
                for (int j = 0; j < 8; j++)
                    acc[i][j] = fmaf(a[i], b[j], acc[i][j]);
        }
        __syncthreads();
    }
#pragma unroll
    for (int i = 0; i < 8; i++) {
        int gr = row0 + ty * 8 + i;
        if (gr < NN) {
            float4 v0 = make_float4(acc[i][0], acc[i][1], acc[i][2], acc[i][3]);
            float4 v1 = make_float4(acc[i][4], acc[i][5], acc[i][6], acc[i][7]);
            *(float4*)(g_h + (size_t)gr * NF + tx * 8)     = v0;
            *(float4*)(g_h + (size_t)gr * NF + tx * 8 + 4) = v1;
        }
    }
}

// ============= per-node attention halves: warp per node =============

__global__ void k_alpha(const float* __restrict__ asv, const float* __restrict__ adv) {
    int gt = blockIdx.x * blockDim.x + threadIdx.x;
    int w = gt >> 5;
    if (w >= NN) return;
    int lane = gt & 31;
    float4 hv = *(const float4*)(g_h + (size_t)w * NF + lane * 4);
    float4 a  = *(const float4*)(asv + lane * 4);
    float4 d  = *(const float4*)(adv + lane * 4);
    float s = hv.x * a.x + hv.y * a.y + hv.z * a.z + hv.w * a.w;
    float t = hv.x * d.x + hv.y * d.y + hv.z * d.z + hv.w * d.w;
#pragma unroll
    for (int off = 4; off >= 1; off >>= 1) {
        s += __shfl_down_sync(0xffffffffu, s, off, 8);
        t += __shfl_down_sync(0xffffffffu, t, off, 8);
    }
    if ((lane & 7) == 0) {
        g_as[w * NH + (lane >> 3)] = s;
        g_ad[w * NH + (lane >> 3)] = t;
    }
}

// ===== aggregation: warp per dst node, single pass (softmax shift-free) =====
// lane handles channels [4*lane, 4*lane+4), head = lane/8.

__global__ void k_agg(const float* __restrict__ bias, float* __restrict__ xout) {
    int gt = blockIdx.x * blockDim.x + threadIdx.x;
    int w = gt >> 5;
    if (w >= NN) return;
    int lane = gt & 31;
    int head = lane >> 3;
    int s0 = g_rowptr[w], s1 = g_rowptr[w + 1];
    float adh = g_ad[w * NH + head];

    float4 acc = make_float4(0.f, 0.f, 0.f, 0.f);
    float denom = 0.f;
    for (int i = s0; i < s1; i++) {
        int src = __ldg(&g_col[i]);
        float e = __ldg(&g_as[src * NH + head]) + adh;
        e = (e > 0.f) ? e : 0.2f * e;               // leaky relu 0.2
        float wt = __expf(e);                        // alphas are O(1): no overflow
        denom += wt;
        float4 hv = *(const float4*)(g_h + (size_t)src * NF + lane * 4);
        acc.x = fmaf(wt, hv.x, acc.x);
        acc.y = fmaf(wt, hv.y, acc.y);
        acc.z = fmaf(wt, hv.z, acc.z);
        acc.w = fmaf(wt, hv.w, acc.w);
    }
    float inv = 1.f / (denom + 1e-16f);
    float4 b4 = *(const float4*)(bias + lane * 4);
    float4 o;
    o.x = acc.x * inv + b4.x;
    o.y = acc.y * inv + b4.y;
    o.z = acc.z * inv + b4.z;
    o.w = acc.w * inv + b4.w;
    // elu
    o.x = (o.x > 0.f) ? o.x : expm1f(o.x);
    o.y = (o.y > 0.f) ? o.y : expm1f(o.y);
    o.z = (o.z > 0.f) ? o.z : expm1f(o.z);
    o.w = (o.w > 0.f) ? o.w : expm1f(o.w);
    *(float4*)(xout + (size_t)w * NF + lane * 4) = o;
}

// ====================== mean pool (batch is sorted) ======================

__global__ void k_pool(float* __restrict__ out) {
    int g = blockIdx.x, t = threadIdx.x;
    int a = g_gstart[g], b = g_gstart[g + 1];
    float s = 0.f;
    for (int n = a; n < b; n++) s += g_xa[(size_t)n * NF + t];
    out[g * NF + t] = s / fmaxf((float)(b - a), 1.f);
}

// ============================ launch ============================

extern "C" void kernel_launch(void* const* d_in, const int* in_sizes, int n_in,
                              void* d_out, int out_size) {
    const float* x   = (const float*)d_in[0];
    const float* Ws  = (const float*)d_in[1];
    const float* asv = (const float*)d_in[2];
    const float* adv = (const float*)d_in[3];
    const float* bia = (const float*)d_in[4];
    const void*  ei  = d_in[5];
    const void*  bat = d_in[6];
    float* out = (float*)d_out;

    void *pa = nullptr, *pb = nullptr;
    cudaGetSymbolAddress(&pa, g_xa);
    cudaGetSymbolAddress(&pb, g_xb);
    float* xa = (float*)pa;
    float* xb = (float*)pb;

    // detect index width, then CSR build (deterministic result set)
    k_detect     <<<1, 32>>>(ei, bat);
    k_init_counts<<<(NN   + 255) / 256, 256>>>();
    k_hist       <<<(NE   + 255) / 256, 256>>>(ei);
    k_scan       <<<1, 1024>>>();
    k_scatter    <<<(NTOT + 255) / 256, 256>>>(ei);
    k_gstart     <<<(NN   + 255) / 256, 256>>>(bat);

    const int GB = (NN + 127) / 128;        // 391
    const int WB = (NN * 32 + 255) / 256;   // 6250

    // layer 0
    k_gemm <<<GB, 256>>>(x, Ws);
    k_alpha<<<WB, 256>>>(asv, adv);
    k_agg  <<<WB, 256>>>(bia, xa);
    // layer 1
    k_gemm <<<GB, 256>>>(xa, Ws + NF * NF);
    k_alpha<<<WB, 256>>>(asv + 128, adv + 128);
    k_agg  <<<WB, 256>>>(bia + NF, xb);
    // layer 2
    k_gemm <<<GB, 256>>>(xb, Ws + 2 * NF * NF);
    k_alpha<<<WB, 256>>>(asv + 256, adv + 256);
    k_agg  <<<WB, 256>>>(bia + 2 * NF, xa);

    k_pool<<<NG, 128>>>(out);
}

// round 3
// speedup vs baseline: 1.2087x; 1.2087x over previous
#include <cuda_runtime.h>
#include <cuda_fp16.h>
#include <math.h>

#define NN   50000
#define NE   1600000
#define NTOT (NE + NN)
#define NG   512
#define NF   128
#define NH   4
#define NBLK ((NN + 255) / 256)   // 196

// ---- scratch (device globals; no allocation allowed) ----
__device__ __half g_hh[(size_t)NN * NF];  // h in fp16 (message tensor)
__device__ float  g_xa[(size_t)NN * NF];  // ping
__device__ float  g_xb[(size_t)NN * NF];  // pong
__device__ float  g_as[NN * NH];
__device__ float  g_ad[NN * NH];
__device__ int    g_rowptr[NN + 1];
__device__ int    g_cursor[NN];
__device__ int    g_col[NTOT];
__device__ int    g_gstart[NG + 1];
__device__ int    g_bsum[256];
__device__ int    g_bpre[256];
__device__ int    g_ei64;
__device__ int    g_bat64;

// ---------- runtime index-width detection (parallel) ----------
__global__ void k_detect(const void* __restrict__ ei, const void* __restrict__ bat) {
    int t = threadIdx.x;
    const unsigned long long* e = (const unsigned long long*)ei;
    const unsigned long long* b = (const unsigned long long*)bat;
    // int64 data: values < 2^31 -> hi word 0. int32 data read as u64: hi word
    // is the next element (node idx / graph id), virtually never all-zero over 256 words.
    int ebad = (e[t] >> 31) != 0ull;
    int bbad = (b[20000 + t] >> 31) != 0ull;   // index safe under both widths
    int anyE = __syncthreads_or(ebad);
    int anyB = __syncthreads_or(bbad);
    if (t == 0) { g_ei64 = !anyE; g_bat64 = !anyB; }
}

__device__ __forceinline__ int load_idx(const void* p, int i, int is64) {
    return is64 ? (int)((const long long*)p)[i] : ((const int*)p)[i];
}

// ============================ CSR build ============================

__global__ void k_init_counts() {
    int i = blockIdx.x * blockDim.x + threadIdx.x;
    if (i < NN) g_cursor[i] = 1;   // self-loop
}

__global__ void k_hist(const void* __restrict__ ei) {
    int i = blockIdx.x * blockDim.x + threadIdx.x;
    if (i < NE) atomicAdd(&g_cursor[load_idx(ei, NE + i, g_ei64)], 1);
}

// ---- 3-phase parallel exclusive scan of g_cursor -> g_rowptr (+reset cursor) ----
__global__ void k_scan1() {   // per-block sums
    __shared__ int sh[256];
    int t = threadIdx.x, i = blockIdx.x * 256 + t;
    sh[t] = (i < NN) ? g_cursor[i] : 0;
    __syncthreads();
    for (int off = 128; off >= 1; off >>= 1) {
        if (t < off) sh[t] += sh[t + off];
        __syncthreads();
    }
    if (t == 0) g_bsum[blockIdx.x] = sh[0];
}

__global__ void k_scan2() {   // scan of 196 block sums (1 block)
    __shared__ int sh[256];
    int t = threadIdx.x;
    int v = (t < NBLK) ? g_bsum[t] : 0;
    sh[t] = v;
    __syncthreads();
    for (int off = 1; off < 256; off <<= 1) {
        int u = (t >= off) ? sh[t - off] : 0;
        __syncthreads();
        sh[t] += u;
        __syncthreads();
    }
    if (t < NBLK) g_bpre[t] = sh[t] - v;      // exclusive
    if (t == 0)  g_rowptr[NN] = NTOT;
}

__global__ void k_scan3() {   // per-block exclusive scan + base
    __shared__ int sh[256];
    int t = threadIdx.x, i = blockIdx.x * 256 + t;
    int v = (i < NN) ? g_cursor[i] : 0;
    sh[t] = v;
    __syncthreads();
    for (int off = 1; off < 256; off <<= 1) {
        int u = (t >= off) ? sh[t - off] : 0;
        __syncthreads();
        sh[t] += u;
        __syncthreads();
    }
    if (i < NN) {
        int r = g_bpre[blockIdx.x] + sh[t] - v;
        g_rowptr[i] = r;
        g_cursor[i] = r;
    }
}

__global__ void k_scatter(const void* __restrict__ ei) {
    int i = blockIdx.x * blockDim.x + threadIdx.x;
    if (i >= NTOT) return;
    int src, dst;
    if (i < NE) {
        int is64 = g_ei64;
        src = load_idx(ei, i, is64);
        dst = load_idx(ei, NE + i, is64);
    } else {
        src = dst = i - NE;
    }
    int p = atomicAdd(&g_cursor[dst], 1);
    g_col[p] = src;
}

__global__ void k_gstart(const void* __restrict__ batch) {
    int i = blockIdx.x * blockDim.x + threadIdx.x;
    if (i >= NN) return;
    int is64 = g_bat64;
    int b  = load_idx(batch, i, is64);
    int bp = (i == 0) ? -1 : load_idx(batch, i - 1, is64);
    for (int g = bp + 1; g <= b; g++) g_gstart[g] = i;
    if (i == NN - 1)
        for (int g = b + 1; g <= NG; g++) g_gstart[g] = NN;
}

// ============== GEMM + fused alpha epilogue: g_hh(half), g_as, g_ad ==============
// 128x128 tile, 256 threads, 8x8 microtile.

__global__ __launch_bounds__(256) void k_gemm(const float* __restrict__ X,
                                              const float* __restrict__ W,
                                              const float* __restrict__ asv,
                                              const float* __restrict__ adv) {
    __shared__ __align__(16) float As[16][128];
    __shared__ __align__(16) float Bs[16][128];
    int tid  = threadIdx.x;
    int tx   = tid & 15, ty = tid >> 4;
    int row0 = blockIdx.x * 128;

    float acc[8][8];
#pragma unroll
    for (int i = 0; i < 8; i++)
#pragma unroll
        for (int j = 0; j < 8; j++) acc[i][j] = 0.f;

    for (int k0 = 0; k0 < 128; k0 += 16) {
#pragma unroll
        for (int l = 0; l < 2; l++) {
            int f4 = tid * 2 + l;
            int r = f4 >> 2, kq = (f4 & 3) << 2;
            int gr = row0 + r;
            float4 v = make_float4(0.f, 0.f, 0.f, 0.f);
            if (gr < NN) v = *(const float4*)(X + (size_t)gr * NF + k0 + kq);
            As[kq + 0][r] = v.x; As[kq + 1][r] = v.y;
            As[kq + 2][r] = v.z; As[kq + 3][r] = v.w;
            int kr = f4 >> 5, nq = (f4 & 31) << 2;
            *(float4*)&Bs[kr][nq] = *(const float4*)(W + (size_t)(k0 + kr) * NF + nq);
        }
        __syncthreads();
#pragma unroll
        for (int kk = 0; kk < 16; kk++) {
            float a[8], b[8];
            *(float4*)&a[0] = *(const float4*)&As[kk][ty * 8];
            *(float4*)&a[4] = *(const float4*)&As[kk][ty * 8 + 4];
            *(float4*)&b[0] = *(const float4*)&Bs[kk][tx * 8];
            *(float4*)&b[4] = *(const float4*)&Bs[kk][tx * 8 + 4];
#pragma unroll
            for (int i = 0; i < 8; i++)
#pragma unroll
                for (int j = 0; j < 8; j++)
                    acc[i][j] = fmaf(a[i], b[j], acc[i][j]);
        }
        __syncthreads();
    }

    // att vectors for my 8 cols (all within one head: tx*8 mod 32 in {0,8,16,24})
    float av[8], dv[8];
#pragma unroll
    for (int j = 0; j < 8; j++) {
        av[j] = asv[tx * 8 + j];
        dv[j] = adv[tx * 8 + j];
    }
    int hd = tx >> 2;

#pragma unroll
    for (int i = 0; i < 8; i++) {
        int gr = row0 + ty * 8 + i;
        // fp16 store of h
        __half2 p0 = __floats2half2_rn(acc[i][0], acc[i][1]);
        __half2 p1 = __floats2half2_rn(acc[i][2], acc[i][3]);
        __half2 p2 = __floats2half2_rn(acc[i][4], acc[i][5]);
        __half2 p3 = __floats2half2_rn(acc[i][6], acc[i][7]);
        // alpha partial dots (fp32, exact)
        float s = 0.f, t = 0.f;
#pragma unroll
        for (int j = 0; j < 8; j++) {
            s = fmaf(acc[i][j], av[j], s);
            t = fmaf(acc[i][j], dv[j], t);
        }
        // reduce across the 4 consecutive lanes sharing this head
        s += __shfl_xor_sync(0xffffffffu, s, 1);
        t += __shfl_xor_sync(0xffffffffu, t, 1);
        s += __shfl_xor_sync(0xffffffffu, s, 2);
        t += __shfl_xor_sync(0xffffffffu, t, 2);
        if (gr < NN) {
            __half2 hv[4] = {p0, p1, p2, p3};
            *(uint4*)(g_hh + (size_t)gr * NF + tx * 8) = *(uint4*)hv;
            if ((tx & 3) == 0) {
                g_as[gr * NH + hd] = s;
                g_ad[gr * NH + hd] = t;
            }
        }
    }
}

// ===== aggregation: warp per dst node, single pass (shift-free softmax) =====
// lane handles channels [4*lane, 4*lane+4), head = lane/8. h gathered in fp16.

__global__ void k_agg(const float* __restrict__ bias, float* __restrict__ xout) {
    int gt = blockIdx.x * blockDim.x + threadIdx.x;
    int w = gt >> 5;
    if (w >= NN) return;
    int lane = gt & 31;
    int head = lane >> 3;
    int s0 = g_rowptr[w], s1 = g_rowptr[w + 1];
    float adh = g_ad[w * NH + head];

    float4 acc = make_float4(0.f, 0.f, 0.f, 0.f);
    float denom = 0.f;
    for (int i = s0; i < s1; i++) {
        int src = __ldg(&g_col[i]);
        float e = __ldg(&g_as[src * NH + head]) + adh;
        e = (e > 0.f) ? e : 0.2f * e;            // leaky relu
        float wt = __expf(e);                    // alphas O(1): no overflow
        denom += wt;
        uint2 raw = __ldg((const uint2*)(g_hh + (size_t)src * NF + lane * 4));
        float2 f0 = __half22float2(*(const __half2*)&raw.x);
        float2 f1 = __half22float2(*(const __half2*)&raw.y);
        acc.x = fmaf(wt, f0.x, acc.x);
        acc.y = fmaf(wt, f0.y, acc.y);
        acc.z = fmaf(wt, f1.x, acc.z);
        acc.w = fmaf(wt, f1.y, acc.w);
    }
    float inv = 1.f / (denom + 1e-16f);
    float4 b4 = *(const float4*)(bias + lane * 4);
    float4 o;
    o.x = acc.x * inv + b4.x;
    o.y = acc.y * inv + b4.y;
    o.z = acc.z * inv + b4.z;
    o.w = acc.w * inv + b4.w;
    o.x = (o.x > 0.f) ? o.x : expm1f(o.x);
    o.y = (o.y > 0.f) ? o.y : expm1f(o.y);
    o.z = (o.z > 0.f) ? o.z : expm1f(o.z);
    o.w = (o.w > 0.f) ? o.w : expm1f(o.w);
    *(float4*)(xout + (size_t)w * NF + lane * 4) = o;
}

// ====================== mean pool (batch is sorted) ======================

__global__ void k_pool(float* __restrict__ out) {
    int g = blockIdx.x, t = threadIdx.x;
    int a = g_gstart[g], b = g_gstart[g + 1];
    float s = 0.f;
    for (int n = a; n < b; n++) s += g_xa[(size_t)n * NF + t];
    out[g * NF + t] = s / fmaxf((float)(b - a), 1.f);
}

// ============================ launch ============================

extern "C" void kernel_launch(void* const* d_in, const int* in_sizes, int n_in,
                              void* d_out, int out_size) {
    const float* x   = (const float*)d_in[0];
    const float* Ws  = (const float*)d_in[1];
    const float* asv = (const float*)d_in[2];
    const float* adv = (const float*)d_in[3];
    const float* bia = (const float*)d_in[4];
    const void*  ei  = d_in[5];
    const void*  bat = d_in[6];
    float* out = (float*)d_out;

    void *pa = nullptr, *pb = nullptr;
    cudaGetSymbolAddress(&pa, g_xa);
    cudaGetSymbolAddress(&pb, g_xb);
    float* xa = (float*)pa;
    float* xb = (float*)pb;

    k_detect     <<<1, 256>>>(ei, bat);
    k_init_counts<<<NBLK, 256>>>();
    k_hist       <<<(NE + 255) / 256, 256>>>(ei);
    k_scan1      <<<NBLK, 256>>>();
    k_scan2      <<<1, 256>>>();
    k_scan3      <<<NBLK, 256>>>();
    k_scatter    <<<(NTOT + 255) / 256, 256>>>(ei);
    k_gstart     <<<NBLK, 256>>>(bat);

    const int GB = (NN + 127) / 128;        // 391
    const int WB = (NN * 32 + 255) / 256;   // 6250

    k_gemm<<<GB, 256>>>(x,  Ws,             asv,       adv);
    k_agg <<<WB, 256>>>(bia, xa);
    k_gemm<<<GB, 256>>>(xa, Ws + NF * NF,   asv + 128, adv + 128);
    k_agg <<<WB, 256>>>(bia + NF, xb);
    k_gemm<<<GB, 256>>>(xb, Ws + 2 * NF * NF, asv + 256, adv + 256);
    k_agg <<<WB, 256>>>(bia + 2 * NF, xa);

    k_pool<<<NG, 128>>>(out);
}

// round 4
// speedup vs baseline: 1.4637x; 1.2110x over previous
#include <cuda_runtime.h>
#include <cuda_fp16.h>
#include <math.h>

#define NN   50000
#define NE   1600000
#define NTOT (NE + NN)
#define NG   512
#define NF   128
#define NH   4
#define NBLK ((NN + 255) / 256)   // 196

// ---- scratch (device globals; no allocation allowed) ----
__device__ __half g_hh [(size_t)NN * NF];  // h messages (fp16)
__device__ __half g_xh0[(size_t)NN * NF];  // input x converted to fp16
__device__ __half g_xha[(size_t)NN * NF];  // ping
__device__ __half g_xhb[(size_t)NN * NF];  // pong
__device__ __half g_wt [3 * NF * NF];      // W transposed [l][n][k], fp16
__device__ float  g_as[NN * NH];
__device__ float  g_ad[NN * NH];
__device__ int    g_rowptr[NN + 1];
__device__ int    g_cursor[NN];
__device__ int    g_col[NTOT];
__device__ int    g_gstart[NG + 1];
__device__ int    g_bsum[256];
__device__ int    g_bpre[256];
__device__ int    g_ei64;
__device__ int    g_bat64;

// ---------- runtime index-width detection ----------
__global__ void k_detect(const void* __restrict__ ei, const void* __restrict__ bat) {
    int t = threadIdx.x;
    const unsigned long long* e = (const unsigned long long*)ei;
    const unsigned long long* b = (const unsigned long long*)bat;
    int ebad = (e[t] >> 31) != 0ull;
    int bbad = (b[20000 + t] >> 31) != 0ull;
    int anyE = __syncthreads_or(ebad);
    int anyB = __syncthreads_or(bbad);
    if (t == 0) { g_ei64 = !anyE; g_bat64 = !anyB; }
}

__device__ __forceinline__ int load_idx(const void* p, int i, int is64) {
    return is64 ? (int)((const long long*)p)[i] : ((const int*)p)[i];
}

// ============================ conversions ============================

__global__ void k_xconv(const float* __restrict__ x) {
    int i = blockIdx.x * blockDim.x + threadIdx.x;       // over NN*NF/4
    if (i >= NN * NF / 4) return;
    float4 v = ((const float4*)x)[i];
    __half2 h0 = __floats2half2_rn(v.x, v.y);
    __half2 h1 = __floats2half2_rn(v.z, v.w);
    uint2 u; u.x = *(unsigned*)&h0; u.y = *(unsigned*)&h1;
    ((uint2*)g_xh0)[i] = u;
}

__global__ void k_wconv(const float* __restrict__ Ws) {
    int i = blockIdx.x * blockDim.x + threadIdx.x;       // over 3*NF*NF
    if (i >= 3 * NF * NF) return;
    int l = i >> 14, r = i & 16383;
    int n = r >> 7, k = r & 127;
    g_wt[i] = __float2half(Ws[l * NF * NF + k * NF + n]);
}

// ============================ CSR build ============================

__global__ void k_init_counts() {
    int i = blockIdx.x * blockDim.x + threadIdx.x;
    if (i < NN) g_cursor[i] = 1;
}

__global__ void k_hist(const void* __restrict__ ei) {
    int i = blockIdx.x * blockDim.x + threadIdx.x;
    if (i < NE) atomicAdd(&g_cursor[load_idx(ei, NE + i, g_ei64)], 1);
}

__global__ void k_scan1() {
    __shared__ int sh[256];
    int t = threadIdx.x, i = blockIdx.x * 256 + t;
    sh[t] = (i < NN) ? g_cursor[i] : 0;
    __syncthreads();
    for (int off = 128; off >= 1; off >>= 1) {
        if (t < off) sh[t] += sh[t + off];
        __syncthreads();
    }
    if (t == 0) g_bsum[blockIdx.x] = sh[0];
}

__global__ void k_scan2() {
    __shared__ int sh[256];
    int t = threadIdx.x;
    int v = (t < NBLK) ? g_bsum[t] : 0;
    sh[t] = v;
    __syncthreads();
    for (int off = 1; off < 256; off <<= 1) {
        int u = (t >= off) ? sh[t - off] : 0;
        __syncthreads();
        sh[t] += u;
        __syncthreads();
    }
    if (t < NBLK) g_bpre[t] = sh[t] - v;
    if (t == 0)  g_rowptr[NN] = NTOT;
}

__global__ void k_scan3() {
    __shared__ int sh[256];
    int t = threadIdx.x, i = blockIdx.x * 256 + t;
    int v = (i < NN) ? g_cursor[i] : 0;
    sh[t] = v;
    __syncthreads();
    for (int off = 1; off < 256; off <<= 1) {
        int u = (t >= off) ? sh[t - off] : 0;
        __syncthreads();
        sh[t] += u;
        __syncthreads();
    }
    if (i < NN) {
        int r = g_bpre[blockIdx.x] + sh[t] - v;
        g_rowptr[i] = r;
        g_cursor[i] = r;
    }
}

__global__ void k_scatter(const void* __restrict__ ei) {
    int i = blockIdx.x * blockDim.x + threadIdx.x;
    if (i >= NTOT) return;
    int src, dst;
    if (i < NE) {
        int is64 = g_ei64;
        src = load_idx(ei, i, is64);
        dst = load_idx(ei, NE + i, is64);
    } else {
        src = dst = i - NE;
    }
    int p = atomicAdd(&g_cursor[dst], 1);
    g_col[p] = src;
}

__global__ void k_gstart(const void* __restrict__ batch) {
    int i = blockIdx.x * blockDim.x + threadIdx.x;
    if (i >= NN) return;
    int is64 = g_bat64;
    int b  = load_idx(batch, i, is64);
    int bp = (i == 0) ? -1 : load_idx(batch, i - 1, is64);
    for (int g = bp + 1; g <= b; g++) g_gstart[g] = i;
    if (i == NN - 1)
        for (int g = b + 1; g <= NG; g++) g_gstart[g] = NN;
}

// ================== tensor-core GEMM + fused alpha epilogue ==================
// C[NN x 128] = A(fp16) x W(fp16), fp32 accum. Block: 128 rows x 128 cols,
// 8 warps in 4(m) x 2(n) grid; warp tile 32x64 = 2 m-tiles x 8 n-tiles of
// mma.sync.m16n8k16. No smem: A frags reused across n-tiles (1 global read
// per element per block); Wt rows L1-resident.

#define MMA16816(C, A, B)                                                   \
    asm volatile(                                                           \
        "mma.sync.aligned.m16n8k16.row.col.f32.f16.f16.f32 "                \
        "{%0,%1,%2,%3}, {%4,%5,%6,%7}, {%8,%9}, {%0,%1,%2,%3};"             \
        : "+f"((C)[0]), "+f"((C)[1]), "+f"((C)[2]), "+f"((C)[3])            \
        : "r"((A)[0]), "r"((A)[1]), "r"((A)[2]), "r"((A)[3]),               \
          "r"((B)[0]), "r"((B)[1]))

__global__ __launch_bounds__(256, 2) void k_gemm(const __half* __restrict__ Ah,
                                                 const __half* __restrict__ Wt,
                                                 const float* __restrict__ asv,
                                                 const float* __restrict__ adv) {
    int tid  = threadIdx.x;
    int w    = tid >> 5, lane = tid & 31;
    int mw   = w >> 1,  nw   = w & 1;
    int g    = lane >> 2, tg = lane & 3;
    int m0   = blockIdx.x * 128 + mw * 32;
    int n0   = nw * 64;

    float c[2][8][4];
#pragma unroll
    for (int mt = 0; mt < 2; mt++)
#pragma unroll
        for (int nt = 0; nt < 8; nt++)
#pragma unroll
            for (int q = 0; q < 4; q++) c[mt][nt][q] = 0.f;

    // clamped row base pointers (stores are guarded; loads just need validity)
    const __half* ap[2][2];
#pragma unroll
    for (int mt = 0; mt < 2; mt++) {
        int r0 = min(m0 + mt * 16 + g,     NN - 1);
        int r1 = min(m0 + mt * 16 + g + 8, NN - 1);
        ap[mt][0] = Ah + (size_t)r0 * NF + 2 * tg;
        ap[mt][1] = Ah + (size_t)r1 * NF + 2 * tg;
    }
    const __half* bp[8];
#pragma unroll
    for (int nt = 0; nt < 8; nt++)
        bp[nt] = Wt + (size_t)(n0 + nt * 8 + g) * NF + 2 * tg;

#pragma unroll
    for (int k0 = 0; k0 < NF; k0 += 16) {
        unsigned a[2][4], b[8][2];
#pragma unroll
        for (int mt = 0; mt < 2; mt++) {
            a[mt][0] = *(const unsigned*)(ap[mt][0] + k0);
            a[mt][1] = *(const unsigned*)(ap[mt][1] + k0);
            a[mt][2] = *(const unsigned*)(ap[mt][0] + k0 + 8);
            a[mt][3] = *(const unsigned*)(ap[mt][1] + k0 + 8);
        }
#pragma unroll
        for (int nt = 0; nt < 8; nt++) {
            b[nt][0] = *(const unsigned*)(bp[nt] + k0);
            b[nt][1] = *(const unsigned*)(bp[nt] + k0 + 8);
        }
#pragma unroll
        for (int mt = 0; mt < 2; mt++)
#pragma unroll
            for (int nt = 0; nt < 8; nt++)
                MMA16816(c[mt][nt], a[mt], b[nt]);
    }

    // ---- epilogue: fp16 h store + fused alpha (fp32-exact) ----
    float av[16], dv[16];
#pragma unroll
    for (int nt = 0; nt < 8; nt++) {
        int col = n0 + nt * 8 + 2 * tg;
        av[2 * nt]     = asv[col];
        av[2 * nt + 1] = asv[col + 1];
        dv[2 * nt]     = adv[col];
        dv[2 * nt + 1] = adv[col + 1];
    }

#pragma unroll
    for (int mt = 0; mt < 2; mt++) {
#pragma unroll
        for (int hr = 0; hr < 2; hr++) {        // row halves g, g+8
            int row = m0 + mt * 16 + g + 8 * hr;
            bool ok = (row < NN);
#pragma unroll
            for (int nt = 0; nt < 8; nt++) {
                __half2 hv = __floats2half2_rn(c[mt][nt][2 * hr], c[mt][nt][2 * hr + 1]);
                if (ok)
                    *(__half2*)(g_hh + (size_t)row * NF + n0 + nt * 8 + 2 * tg) = hv;
            }
#pragma unroll
            for (int hh = 0; hh < 2; hh++) {    // heads within this warp's 64 cols
                float s = 0.f, t = 0.f;
#pragma unroll
                for (int q = 0; q < 4; q++) {
                    int nt = hh * 4 + q;
                    s = fmaf(c[mt][nt][2 * hr], av[2 * nt], s);
                    s = fmaf(c[mt][nt][2 * hr + 1], av[2 * nt + 1], s);
                    t = fmaf(c[mt][nt][2 * hr], dv[2 * nt], t);
                    t = fmaf(c[mt][nt][2 * hr + 1], dv[2 * nt + 1], t);
                }
                s += __shfl_xor_sync(0xffffffffu, s, 1);
                t += __shfl_xor_sync(0xffffffffu, t, 1);
                s += __shfl_xor_sync(0xffffffffu, s, 2);
                t += __shfl_xor_sync(0xffffffffu, t, 2);
                if (ok && tg == 0) {
                    int head = 2 * nw + hh;
                    g_as[row * NH + head] = s;
                    g_ad[row * NH + head] = t;
                }
            }
        }
    }
}

// ===== aggregation: warp per dst node, shift-free softmax, fp16 in/out =====

__global__ void k_agg(const float* __restrict__ bias, __half* __restrict__ xout) {
    int gt = blockIdx.x * blockDim.x + threadIdx.x;
    int w = gt >> 5;
    if (w >= NN) return;
    int lane = gt & 31;
    int head = lane >> 3;
    int s0 = g_rowptr[w], s1 = g_rowptr[w + 1];
    float adh = g_ad[w * NH + head];

    float4 acc = make_float4(0.f, 0.f, 0.f, 0.f);
    float denom = 0.f;
    int src_next = __ldg(&g_col[s0]);           // s1 > s0 always (self-loop)
    for (int i = s0; i < s1; i++) {
        int src = src_next;
        if (i + 1 < s1) src_next = __ldg(&g_col[i + 1]);
        float e = __ldg(&g_as[src * NH + head]) + adh;
        e = (e > 0.f) ? e : 0.2f * e;
        float wt = __expf(e);
        denom += wt;
        uint2 raw = __ldg((const uint2*)(g_hh + (size_t)src * NF + lane * 4));
        float2 f0 = __half22float2(*(const __half2*)&raw.x);
        float2 f1 = __half22float2(*(const __half2*)&raw.y);
        acc.x = fmaf(wt, f0.x, acc.x);
        acc.y = fmaf(wt, f0.y, acc.y);
        acc.z = fmaf(wt, f1.x, acc.z);
        acc.w = fmaf(wt, f1.y, acc.w);
    }
    float inv = 1.f / (denom + 1e-16f);
    float4 b4 = *(const float4*)(bias + lane * 4);
    float4 o;
    o.x = acc.x * inv + b4.x;
    o.y = acc.y * inv + b4.y;
    o.z = acc.z * inv + b4.z;
    o.w = acc.w * inv + b4.w;
    o.x = (o.x > 0.f) ? o.x : expm1f(o.x);
    o.y = (o.y > 0.f) ? o.y : expm1f(o.y);
    o.z = (o.z > 0.f) ? o.z : expm1f(o.z);
    o.w = (o.w > 0.f) ? o.w : expm1f(o.w);
    __half2 h0 = __floats2half2_rn(o.x, o.y);
    __half2 h1 = __floats2half2_rn(o.z, o.w);
    uint2 u; u.x = *(unsigned*)&h0; u.y = *(unsigned*)&h1;
    *(uint2*)(xout + (size_t)w * NF + lane * 4) = u;
}

// ====================== mean pool (batch is sorted) ======================

__global__ void k_pool(const __half* __restrict__ xin, float* __restrict__ out) {
    int g = blockIdx.x, t = threadIdx.x;
    int a = g_gstart[g], b = g_gstart[g + 1];
    float s = 0.f;
    for (int n = a; n < b; n++) s += __half2float(xin[(size_t)n * NF + t]);
    out[g * NF + t] = s / fmaxf((float)(b - a), 1.f);
}

// ============================ launch ============================

extern "C" void kernel_launch(void* const* d_in, const int* in_sizes, int n_in,
                              void* d_out, int out_size) {
    const float* x   = (const float*)d_in[0];
    const float* Ws  = (const float*)d_in[1];
    const float* asv = (const float*)d_in[2];
    const float* adv = (const float*)d_in[3];
    const float* bia = (const float*)d_in[4];
    const void*  ei  = d_in[5];
    const void*  bat = d_in[6];
    float* out = (float*)d_out;

    void *p0 = nullptr, *pa = nullptr, *pb = nullptr, *pw = nullptr;
    cudaGetSymbolAddress(&p0, g_xh0);
    cudaGetSymbolAddress(&pa, g_xha);
    cudaGetSymbolAddress(&pb, g_xhb);
    cudaGetSymbolAddress(&pw, g_wt);
    __half* xh0 = (__half*)p0;
    __half* xha = (__half*)pa;
    __half* xhb = (__half*)pb;
    __half* wt  = (__half*)pw;

    // conversions + CSR build
    k_xconv      <<<(NN * NF / 4 + 255) / 256, 256>>>(x);
    k_wconv      <<<(3 * NF * NF + 255) / 256, 256>>>(Ws);
    k_detect     <<<1, 256>>>(ei, bat);
    k_init_counts<<<NBLK, 256>>>();
    k_hist       <<<(NE + 255) / 256, 256>>>(ei);
    k_scan1      <<<NBLK, 256>>>();
    k_scan2      <<<1, 256>>>();
    k_scan3      <<<NBLK, 256>>>();
    k_scatter    <<<(NTOT + 255) / 256, 256>>>(ei);
    k_gstart     <<<NBLK, 256>>>(bat);

    const int GB = (NN + 127) / 128;        // 391
    const int WB = (NN * 32 + 255) / 256;   // 6250

    k_gemm<<<GB, 256>>>(xh0, wt,               asv,       adv);
    k_agg <<<WB, 256>>>(bia, xha);
    k_gemm<<<GB, 256>>>(xha, wt + NF * NF,     asv + 128, adv + 128);
    k_agg <<<WB, 256>>>(bia + NF, xhb);
    k_gemm<<<GB, 256>>>(xhb, wt + 2 * NF * NF, asv + 256, adv + 256);
    k_agg <<<WB, 256>>>(bia + 2 * NF, xha);

    k_pool<<<NG, 128>>>(xha, out);
}

// round 5
// speedup vs baseline: 1.5619x; 1.0671x over previous
#include <cuda_runtime.h>
#include <cuda_fp16.h>
#include <math.h>

#define NN   50000
#define NE   1600000
#define NTOT (NE + NN)
#define NG   512
#define NF   128
#define NH   4
#define NNP  50048                      // 391 * 128 (row padding for tiles)
#define NBZ  196                        // zero-cursor blocks
#define NBW  192                        // wconv blocks (3*128*128/256)
#define NBX  6250                       // xconv blocks (NN*32/256)
#define NBS  6446                       // scatter blocks ((NTOT+255)/256)

// ---- scratch (device globals; no allocation allowed) ----
__device__ __half g_hh [(size_t)NN * NF];    // h messages, row-major (gather tensor)
__device__ __half g_xh0[(size_t)NNP * NF];   // tiled act: input x (later: row-major pool input)
__device__ __half g_xha[(size_t)NNP * NF];   // tiled act ping
__device__ __half g_xhb[(size_t)NNP * NF];   // tiled act pong
__device__ __half g_wt [3 * NF * NF];        // W in B-fragment tiles
__device__ float  g_as[NN * NH];
__device__ float  g_ad[NN * NH];
__device__ int    g_rowptr[NN + 1];
__device__ int    g_cursor[NN];
__device__ int    g_col[NTOT];
__device__ int    g_gstart[NG + 1];
__device__ int    g_ei64;
__device__ int    g_bat64;

__device__ __forceinline__ int load_idx(const void* p, int i, int is64) {
    return is64 ? (int)((const long long*)p)[i] : ((const int*)p)[i];
}

// tiled activation: 16x16 tile = 256 halfs; lane l=(g*4+tg) owns uint4 (regs a0..a3)
// half offset of (r,c): tile(r>>4, c>>4)*256 + ((r&7)*4 + ((c&7)>>1))*8 + ((r>>3&1) + 2*(c>>3&1))*2 + (c&1)

// ================= prep: detect + zero cursor + xconv + wconv =================
__global__ void k_prep(const float* __restrict__ x, const float* __restrict__ Ws,
                       const void* __restrict__ ei, const void* __restrict__ bat) {
    int bid = blockIdx.x, t = threadIdx.x;
    if (bid == 0) {                           // index-width detect
        const unsigned long long* e = (const unsigned long long*)ei;
        const unsigned long long* b = (const unsigned long long*)bat;
        int ebad = (e[t] >> 31) != 0ull;
        int bbad = (b[20000 + t] >> 31) != 0ull;
        int anyE = __syncthreads_or(ebad);
        int anyB = __syncthreads_or(bbad);
        if (t == 0) { g_ei64 = !anyE; g_bat64 = !anyB; }
        return;
    }
    if (bid <= NBZ) {                         // zero edge-count cursor
        int i = (bid - 1) * 256 + t;
        if (i < NN) g_cursor[i] = 0;
        return;
    }
    if (bid <= NBZ + NBW) {                   // W -> B-fragment tiles (transposed)
        int i = (bid - 1 - NBZ) * 256 + t;    // over 3*128*128
        int l = i >> 14, k = (i >> 7) & 127, n = i & 127;
        g_wt[l * 16384 + (((n >> 3) * 8 + (k >> 4)) << 7)
             + (((n & 7) * 4 + ((k & 7) >> 1)) << 2)
             + (((k >> 3) & 1) << 1) + (k & 1)]
            = __float2half(Ws[l * 16384 + (k << 7) + n]);
        return;
    }
    {                                          // x -> fp16 tiled
        int i = (bid - 1 - NBZ - NBW) * 256 + t;   // over NN*32
        if (i >= NN * 32) return;
        int r = i >> 5, j = i & 31, c0 = j << 2;
        float4 v = ((const float4*)x)[i];
        __half2 h0 = __floats2half2_rn(v.x, v.y);
        __half2 h1 = __floats2half2_rn(v.z, v.w);
        int rt = r >> 4, ri = r & 15, g = ri & 7, hb = ri >> 3;
        int kt = c0 >> 4, cc = c0 & 15, kb = cc >> 3, tg = (cc & 7) >> 1;
        size_t off = (((size_t)rt * 8 + kt) << 8) + (((g << 2) + tg) << 3) + ((hb + (kb << 1)) << 1);
        *(unsigned*)(g_xh0 + off)     = *(unsigned*)&h0;
        *(unsigned*)(g_xh0 + off + 8) = *(unsigned*)&h1;
    }
}

// ============================ CSR build ============================

__global__ void k_hist(const void* __restrict__ ei) {
    int i = blockIdx.x * blockDim.x + threadIdx.x;
    if (i < NE) atomicAdd(&g_cursor[load_idx(ei, NE + i, g_ei64)], 1);
}

// single-block scan: rowptr[i] = prefix(edge counts) + i (self-loop folded in)
__global__ void k_scan_all() {
    __shared__ int wsum[32], wpre[32];
    int t = threadIdx.x, w = t >> 5, lane = t & 31;
    const int CW = 1568;                       // 32*49; 32 warps cover 50176 >= NN
    int base = w * CW, end = min(base + CW, NN);
    int s = 0;
    for (int i = base + lane; i < end; i += 32) s += g_cursor[i];
#pragma unroll
    for (int o = 16; o; o >>= 1) s += __shfl_xor_sync(~0u, s, o);
    if (lane == 0) wsum[w] = s;
    __syncthreads();
    if (w == 0) {
        int v = wsum[lane], incl = v;
#pragma unroll
        for (int o = 1; o < 32; o <<= 1) {
            int u = __shfl_up_sync(~0u, incl, o);
            if (lane >= o) incl += u;
        }
        wpre[lane] = incl - v;
    }
    __syncthreads();
    int run = wpre[w];
    for (int i0 = base; i0 < end; i0 += 32) {
        int i = i0 + lane;
        int v = (i < end) ? g_cursor[i] : 0;
        int incl = v;
#pragma unroll
        for (int o = 1; o < 32; o <<= 1) {
            int u = __shfl_up_sync(~0u, incl, o);
            if (lane >= o) incl += u;
        }
        if (i < end) {
            int r = run + incl - v + i;
            g_rowptr[i] = r;
            g_cursor[i] = r;
        }
        run += __shfl_sync(~0u, incl, 31);
    }
    if (t == 0) g_rowptr[NN] = NTOT;
}

// fused scatter + gstart
__global__ void k_scatgst(const void* __restrict__ ei, const void* __restrict__ batch) {
    int bid = blockIdx.x, t = threadIdx.x;
    if (bid < NBZ) {                           // gstart role
        int i = bid * 256 + t;
        if (i >= NN) return;
        int is64 = g_bat64;
        int b  = load_idx(batch, i, is64);
        int bp = (i == 0) ? -1 : load_idx(batch, i - 1, is64);
        for (int g = bp + 1; g <= b; g++) g_gstart[g] = i;
        if (i == NN - 1)
            for (int g = b + 1; g <= NG; g++) g_gstart[g] = NN;
        return;
    }
    int i = (bid - NBZ) * 256 + t;             // scatter role
    if (i >= NTOT) return;
    int src, dst;
    if (i < NE) {
        int is64 = g_ei64;
        src = load_idx(ei, i, is64);
        dst = load_idx(ei, NE + i, is64);
    } else {
        src = dst = i - NE;                    // self-loop
    }
    int p = atomicAdd(&g_cursor[dst], 1);
    g_col[p] = src;
}

// ================== tensor-core GEMM + fused alpha epilogue ==================
// A in tiled fragment layout (coalesced LDG.128), Wt in B-fragment tiles
// (coalesced LDG.64). Block 128x128, 8 warps 4(m)x2(n), warp 32x64.

#define MMA16816(C, A, B)                                                   \
    asm volatile(                                                           \
        "mma.sync.aligned.m16n8k16.row.col.f32.f16.f16.f32 "                \
        "{%0,%1,%2,%3}, {%4,%5,%6,%7}, {%8,%9}, {%0,%1,%2,%3};"             \
        : "+f"((C)[0]), "+f"((C)[1]), "+f"((C)[2]), "+f"((C)[3])            \
        : "r"((A)[0]), "r"((A)[1]), "r"((A)[2]), "r"((A)[3]),               \
          "r"((B)[0]), "r"((B)[1]))

__global__ __launch_bounds__(256, 2) void k_gemm(const __half* __restrict__ Ah,
                                                 const __half* __restrict__ Wt,
                                                 const float* __restrict__ asv,
                                                 const float* __restrict__ adv) {
    int tid  = threadIdx.x;
    int w    = tid >> 5, lane = tid & 31;
    int mw   = w >> 1,  nw   = w & 1;
    int g    = lane >> 2, tg = lane & 3;
    int m0   = blockIdx.x * 128 + mw * 32;
    int n0   = nw * 64;
    int rt0  = m0 >> 4;

    float c[2][8][4];
#pragma unroll
    for (int mt = 0; mt < 2; mt++)
#pragma unroll
        for (int nt = 0; nt < 8; nt++)
#pragma unroll
            for (int q = 0; q < 4; q++) c[mt][nt][q] = 0.f;

#pragma unroll
    for (int kt = 0; kt < 8; kt++) {
        unsigned a[2][4];
#pragma unroll
        for (int mt = 0; mt < 2; mt++) {
            uint4 v = *(const uint4*)(Ah + ((((size_t)(rt0 + mt)) * 8 + kt) << 8) + (lane << 3));
            a[mt][0] = v.x; a[mt][1] = v.y; a[mt][2] = v.z; a[mt][3] = v.w;
        }
#pragma unroll
        for (int nt = 0; nt < 8; nt++) {
            uint2 vb = *(const uint2*)(Wt + ((((nw * 8 + nt) * 8) + kt) << 7) + (lane << 2));
            unsigned b[2] = {vb.x, vb.y};
            MMA16816(c[0][nt], a[0], b);
            MMA16816(c[1][nt], a[1], b);
        }
    }

    // ---- epilogue: row-major fp16 h store + fused alpha (fp32-exact) ----
    float av[16], dv[16];
#pragma unroll
    for (int nt = 0; nt < 8; nt++) {
        int col = n0 + nt * 8 + 2 * tg;
        av[2 * nt]     = asv[col];
        av[2 * nt + 1] = asv[col + 1];
        dv[2 * nt]     = adv[col];
        dv[2 * nt + 1] = adv[col + 1];
    }

#pragma unroll
    for (int mt = 0; mt < 2; mt++) {
#pragma unroll
        for (int hr = 0; hr < 2; hr++) {
            int row = m0 + mt * 16 + g + 8 * hr;
            bool ok = (row < NN);
#pragma unroll
            for (int nt = 0; nt < 8; nt++) {
                __half2 hv = __floats2half2_rn(c[mt][nt][2 * hr], c[mt][nt][2 * hr + 1]);
                if (ok)
                    *(__half2*)(g_hh + (size_t)row * NF + n0 + nt * 8 + 2 * tg) = hv;
            }
#pragma unroll
            for (int hh = 0; hh < 2; hh++) {
                float s = 0.f, t = 0.f;
#pragma unroll
                for (int q = 0; q < 4; q++) {
                    int nt = hh * 4 + q;
                    s = fmaf(c[mt][nt][2 * hr], av[2 * nt], s);
                    s = fmaf(c[mt][nt][2 * hr + 1], av[2 * nt + 1], s);
                    t = fmaf(c[mt][nt][2 * hr], dv[2 * nt], t);
                    t = fmaf(c[mt][nt][2 * hr + 1], dv[2 * nt + 1], t);
                }
                s += __shfl_xor_sync(0xffffffffu, s, 1);
                t += __shfl_xor_sync(0xffffffffu, t, 1);
                s += __shfl_xor_sync(0xffffffffu, s, 2);
                t += __shfl_xor_sync(0xffffffffu, t, 2);
                if (ok && tg == 0) {
                    int head = 2 * nw + hh;
                    g_as[row * NH + head] = s;
                    g_ad[row * NH + head] = t;
                }
            }
        }
    }
}

// ===== aggregation: warp per dst node, shift-free softmax, pipelined gather =====
// writes tiled activation (for next GEMM); if rm != null also row-major (pool input)

__global__ void k_agg(const float* __restrict__ bias, __half* __restrict__ xout,
                      __half* __restrict__ rm) {
    int gt = blockIdx.x * blockDim.x + threadIdx.x;
    int w = gt >> 5;
    if (w >= NN) return;
    int lane = gt & 31;
    int head = lane >> 3;
    int s0 = g_rowptr[w], s1 = g_rowptr[w + 1];
    float adh = g_ad[w * NH + head];

    float4 acc = make_float4(0.f, 0.f, 0.f, 0.f);
    float denom = 0.f;
    // prologue of 1-deep software pipeline (s1 > s0 always: self-loop)
    int   srcC = __ldg(&g_col[s0]);
    uint2 rawC = __ldg((const uint2*)(g_hh + (size_t)srcC * NF + lane * 4));
    float asC  = __ldg(&g_as[srcC * NH + head]);
    for (int i = s0; i < s1; i++) {
        int srcN = 0; uint2 rawN; float asN = 0.f;
        if (i + 1 < s1) {
            srcN = __ldg(&g_col[i + 1]);
            rawN = __ldg((const uint2*)(g_hh + (size_t)srcN * NF + lane * 4));
            asN  = __ldg(&g_as[srcN * NH + head]);
        }
        float e = asC + adh;
        e = (e > 0.f) ? e : 0.2f * e;
        float wt = __expf(e);
        denom += wt;
        float2 f0 = __half22float2(*(const __half2*)&rawC.x);
        float2 f1 = __half22float2(*(const __half2*)&rawC.y);
        acc.x = fmaf(wt, f0.x, acc.x);
        acc.y = fmaf(wt, f0.y, acc.y);
        acc.z = fmaf(wt, f1.x, acc.z);
        acc.w = fmaf(wt, f1.y, acc.w);
        srcC = srcN; rawC = rawN; asC = asN;
    }
    float inv = 1.f / (denom + 1e-16f);
    float4 b4 = *(const float4*)(bias + lane * 4);
    float4 o;
    o.x = acc.x * inv + b4.x;
    o.y = acc.y * inv + b4.y;
    o.z = acc.z * inv + b4.z;
    o.w = acc.w * inv + b4.w;
    o.x = (o.x > 0.f) ? o.x : expm1f(o.x);
    o.y = (o.y > 0.f) ? o.y : expm1f(o.y);
    o.z = (o.z > 0.f) ? o.z : expm1f(o.z);
    o.w = (o.w > 0.f) ? o.w : expm1f(o.w);
    __half2 h0 = __floats2half2_rn(o.x, o.y);
    __half2 h1 = __floats2half2_rn(o.z, o.w);
    if (rm) {                                   // final layer: row-major for pool
        uint2 u; u.x = *(unsigned*)&h0; u.y = *(unsigned*)&h1;
        *(uint2*)(rm + (size_t)w * NF + lane * 4) = u;
    } else {                                    // tiled for next GEMM
        int c0 = lane << 2;
        int rt = w >> 4, ri = w & 15, g = ri & 7, hb = ri >> 3;
        int kt = c0 >> 4, cc = c0 & 15, kb = cc >> 3, tg = (cc & 7) >> 1;
        size_t off = (((size_t)rt * 8 + kt) << 8) + (((g << 2) + tg) << 3) + ((hb + (kb << 1)) << 1);
        *(unsigned*)(xout + off)     = *(unsigned*)&h0;
        *(unsigned*)(xout + off + 8) = *(unsigned*)&h1;
    }
}

// ====================== mean pool (batch is sorted) ======================

__global__ void k_pool(const __half* __restrict__ xin, float* __restrict__ out) {
    int g = blockIdx.x, t = threadIdx.x;
    int a = g_gstart[g], b = g_gstart[g + 1];
    float s = 0.f;
    for (int n = a; n < b; n++) s += __half2float(xin[(size_t)n * NF + t]);
    out[g * NF + t] = s / fmaxf((float)(b - a), 1.f);
}

// ============================ launch ============================

extern "C" void kernel_launch(void* const* d_in, const int* in_sizes, int n_in,
                              void* d_out, int out_size) {
    const float* x   = (const float*)d_in[0];
    const float* Ws  = (const float*)d_in[1];
    const float* asv = (const float*)d_in[2];
    const float* adv = (const float*)d_in[3];
    const float* bia = (const float*)d_in[4];
    const void*  ei  = d_in[5];
    const void*  bat = d_in[6];
    float* out = (float*)d_out;

    void *p0 = nullptr, *pa = nullptr, *pb = nullptr, *pw = nullptr;
    cudaGetSymbolAddress(&p0, g_xh0);
    cudaGetSymbolAddress(&pa, g_xha);
    cudaGetSymbolAddress(&pb, g_xhb);
    cudaGetSymbolAddress(&pw, g_wt);
    __half* xh0 = (__half*)p0;
    __half* xha = (__half*)pa;
    __half* xhb = (__half*)pb;
    __half* wt  = (__half*)pw;

    k_prep    <<<1 + NBZ + NBW + NBX, 256>>>(x, Ws, ei, bat);
    k_hist    <<<(NE + 255) / 256, 256>>>(ei);
    k_scan_all<<<1, 1024>>>();
    k_scatgst <<<NBZ + NBS, 256>>>(ei, bat);

    const int GB = (NN + 127) / 128;        // 391
    const int WB = (NN * 32 + 255) / 256;   // 6250

    k_gemm<<<GB, 256>>>(xh0, wt,               asv,       adv);
    k_agg <<<WB, 256>>>(bia, xha, nullptr);
    k_gemm<<<GB, 256>>>(xha, wt + NF * NF,     asv + 128, adv + 128);
    k_agg <<<WB, 256>>>(bia + NF, xhb, nullptr);
    k_gemm<<<GB, 256>>>(xhb, wt + 2 * NF * NF, asv + 256, adv + 256);
    k_agg <<<WB, 256>>>(bia + 2 * NF, nullptr, xh0);

    k_pool<<<NG, 128>>>(xh0, out);
}

// round 6
// speedup vs baseline: 1.6340x; 1.0462x over previous
#include <cuda_runtime.h>
#include <cuda_fp16.h>
#include <math.h>

#define NN   50000
#define NE   1600000
#define NTOT (NE + NN)
#define NG   512
#define NF   128
#define NH   4
#define NNP  50048                      // 391 * 128 (row padding for tiles)
#define NBZ  196                        // zero-cursor / gstart blocks
#define NBW  192                        // wconv blocks (3*128*128/256)
#define NBX  6250                       // xconv blocks (NN*32/256)
#define NB4H 1563                       // hist blocks   (NE/4/256)
#define NB4S 1612                       // scatter blocks (ceil(NTOT/4)/256)

// ---- scratch (device globals; no allocation allowed) ----
__device__ __half g_hh [(size_t)NN * NF];    // h messages, row-major (gather tensor)
__device__ __half g_xh0[(size_t)NNP * NF];   // tiled act: input x (later: row-major pool input)
__device__ __half g_xha[(size_t)NNP * NF];   // tiled act ping
__device__ __half g_xhb[(size_t)NNP * NF];   // tiled act pong
__device__ __half g_wt [3 * NF * NF];        // W in B-fragment tiles
__device__ float  g_as[NN * NH];
__device__ float  g_ad[NN * NH];
__device__ int    g_rowptr[NN + 1];
__device__ int    g_cursor[NN];
__device__ int    g_col[NTOT];
__device__ int    g_gstart[NG + 1];
__device__ int    g_ei64;
__device__ int    g_bat64;

__device__ __forceinline__ int load_idx(const void* p, int i, int is64) {
    return is64 ? (int)((const long long*)p)[i] : ((const int*)p)[i];
}

// tiled activation: 16x16 tile = 256 halfs; lane l=(g*4+tg) owns uint4
// half offset of (r,c): tile(r>>4,c>>4)*256 + ((r&7)*4+((c&7)>>1))*8 + ((r>>3&1)+2*(c>>3&1))*2 + (c&1)

// ================= prep: detect + zero cursor + xconv + wconv =================
__global__ void k_prep(const float* __restrict__ x, const float* __restrict__ Ws,
                       const void* __restrict__ ei, const void* __restrict__ bat) {
    int bid = blockIdx.x, t = threadIdx.x;
    if (bid == 0) {                           // index-width detect
        const unsigned long long* e = (const unsigned long long*)ei;
        const unsigned long long* b = (const unsigned long long*)bat;
        int ebad = (e[t] >> 31) != 0ull;
        int bbad = (b[20000 + t] >> 31) != 0ull;
        int anyE = __syncthreads_or(ebad);
        int anyB = __syncthreads_or(bbad);
        if (t == 0) { g_ei64 = !anyE; g_bat64 = !anyB; }
        return;
    }
    if (bid <= NBZ) {                         // zero edge-count cursor
        int i = (bid - 1) * 256 + t;
        if (i < NN) g_cursor[i] = 0;
        return;
    }
    if (bid <= NBZ + NBW) {                   // W -> B-fragment tiles (transposed)
        int i = (bid - 1 - NBZ) * 256 + t;    // over 3*128*128
        int l = i >> 14, k = (i >> 7) & 127, n = i & 127;
        g_wt[l * 16384 + (((n >> 3) * 8 + (k >> 4)) << 7)
             + (((n & 7) * 4 + ((k & 7) >> 1)) << 2)
             + (((k >> 3) & 1) << 1) + (k & 1)]
            = __float2half(Ws[l * 16384 + (k << 7) + n]);
        return;
    }
    {                                          // x -> fp16 tiled
        int i = (bid - 1 - NBZ - NBW) * 256 + t;   // over NN*32
        if (i >= NN * 32) return;
        int r = i >> 5, j = i & 31, c0 = j << 2;
        float4 v = ((const float4*)x)[i];
        __half2 h0 = __floats2half2_rn(v.x, v.y);
        __half2 h1 = __floats2half2_rn(v.z, v.w);
        int rt = r >> 4, ri = r & 15, g = ri & 7, hb = ri >> 3;
        int kt = c0 >> 4, cc = c0 & 15, kb = cc >> 3, tg = (cc & 7) >> 1;
        size_t off = (((size_t)rt * 8 + kt) << 8) + (((g << 2) + tg) << 3) + ((hb + (kb << 1)) << 1);
        *(unsigned*)(g_xh0 + off)     = *(unsigned*)&h0;
        *(unsigned*)(g_xh0 + off + 8) = *(unsigned*)&h1;
    }
}

// ============================ CSR build ============================

// histogram of dst, 4 edges/thread with vector loads (MLP=4)
__global__ void k_hist(const void* __restrict__ ei) {
    int base = (blockIdx.x * blockDim.x + threadIdx.x) * 4;
    if (base >= NE) return;
    int is64 = g_ei64;
    int d0, d1, d2, d3;
    if (base + 3 < NE) {
        if (is64) {
            const longlong2* p = (const longlong2*)ei + ((size_t)NE + base) / 2;
            longlong2 a = __ldg(p), b = __ldg(p + 1);
            d0 = (int)a.x; d1 = (int)a.y; d2 = (int)b.x; d3 = (int)b.y;
        } else {
            int4 a = __ldg((const int4*)((const int*)ei + NE) + base / 4);
            d0 = a.x; d1 = a.y; d2 = a.z; d3 = a.w;
        }
        atomicAdd(&g_cursor[d0], 1);
        atomicAdd(&g_cursor[d1], 1);
        atomicAdd(&g_cursor[d2], 1);
        atomicAdd(&g_cursor[d3], 1);
    } else {
        for (int j = 0; j < 4 && base + j < NE; j++)
            atomicAdd(&g_cursor[load_idx(ei, NE + base + j, is64)], 1);
    }
}

// single-block scan: rowptr[i] = prefix(edge counts) + i (self-loop folded in)
__global__ void k_scan_all() {
    __shared__ int wsum[32], wpre[32];
    int t = threadIdx.x, w = t >> 5, lane = t & 31;
    const int CW = 1568;
    int base = w * CW, end = min(base + CW, NN);
    int s = 0;
    for (int i = base + lane; i < end; i += 32) s += g_cursor[i];
#pragma unroll
    for (int o = 16; o; o >>= 1) s += __shfl_xor_sync(~0u, s, o);
    if (lane == 0) wsum[w] = s;
    __syncthreads();
    if (w == 0) {
        int v = wsum[lane], incl = v;
#pragma unroll
        for (int o = 1; o < 32; o <<= 1) {
            int u = __shfl_up_sync(~0u, incl, o);
            if (lane >= o) incl += u;
        }
        wpre[lane] = incl - v;
    }
    __syncthreads();
    int run = wpre[w];
    for (int i0 = base; i0 < end; i0 += 32) {
        int i = i0 + lane;
        int v = (i < end) ? g_cursor[i] : 0;
        int incl = v;
#pragma unroll
        for (int o = 1; o < 32; o <<= 1) {
            int u = __shfl_up_sync(~0u, incl, o);
            if (lane >= o) incl += u;
        }
        if (i < end) {
            int r = run + incl - v + i;
            g_rowptr[i] = r;
            g_cursor[i] = r;
        }
        run += __shfl_sync(~0u, incl, 31);
    }
    if (t == 0) g_rowptr[NN] = NTOT;
}

// fused scatter (4 items/thread, MLP=4) + gstart
__global__ void k_scatgst(const void* __restrict__ ei, const void* __restrict__ batch) {
    int bid = blockIdx.x, t = threadIdx.x;
    if (bid < NBZ) {                           // gstart role
        int i = bid * 256 + t;
        if (i >= NN) return;
        int is64 = g_bat64;
        int b  = load_idx(batch, i, is64);
        int bp = (i == 0) ? -1 : load_idx(batch, i - 1, is64);
        for (int g = bp + 1; g <= b; g++) g_gstart[g] = i;
        if (i == NN - 1)
            for (int g = b + 1; g <= NG; g++) g_gstart[g] = NN;
        return;
    }
    int base = ((bid - NBZ) * 256 + t) * 4;
    if (base >= NTOT) return;
    int is64 = g_ei64;
    if (base + 3 < NE) {
        int s0, s1, s2, s3, d0, d1, d2, d3;
        if (is64) {
            const longlong2* ps = (const longlong2*)ei + base / 2;
            const longlong2* pd = (const longlong2*)ei + ((size_t)NE + base) / 2;
            longlong2 a = __ldg(ps), b = __ldg(ps + 1);
            longlong2 c = __ldg(pd), d = __ldg(pd + 1);
            s0 = (int)a.x; s1 = (int)a.y; s2 = (int)b.x; s3 = (int)b.y;
            d0 = (int)c.x; d1 = (int)c.y; d2 = (int)d.x; d3 = (int)d.y;
        } else {
            int4 a = __ldg((const int4*)ei + base / 4);
            int4 c = __ldg((const int4*)((const int*)ei + NE) + base / 4);
            s0 = a.x; s1 = a.y; s2 = a.z; s3 = a.w;
            d0 = c.x; d1 = c.y; d2 = c.z; d3 = c.w;
        }
        int p0 = atomicAdd(&g_cursor[d0], 1);
        int p1 = atomicAdd(&g_cursor[d1], 1);
        int p2 = atomicAdd(&g_cursor[d2], 1);
        int p3 = atomicAdd(&g_cursor[d3], 1);
        g_col[p0] = s0; g_col[p1] = s1; g_col[p2] = s2; g_col[p3] = s3;
    } else {
        for (int j = 0; j < 4; j++) {
            int i = base + j;
            if (i >= NTOT) break;
            int src, dst;
            if (i < NE) {
                src = load_idx(ei, i, is64);
                dst = load_idx(ei, NE + i, is64);
            } else {
                src = dst = i - NE;            // self-loop
            }
            int p = atomicAdd(&g_cursor[dst], 1);
            g_col[p] = src;
        }
    }
}

// ================== tensor-core GEMM + fused alpha epilogue ==================

#define MMA16816(C, A, B)                                                   \
    asm volatile(                                                           \
        "mma.sync.aligned.m16n8k16.row.col.f32.f16.f16.f32 "                \
        "{%0,%1,%2,%3}, {%4,%5,%6,%7}, {%8,%9}, {%0,%1,%2,%3};"             \
        : "+f"((C)[0]), "+f"((C)[1]), "+f"((C)[2]), "+f"((C)[3])            \
        : "r"((A)[0]), "r"((A)[1]), "r"((A)[2]), "r"((A)[3]),               \
          "r"((B)[0]), "r"((B)[1]))

__global__ __launch_bounds__(256, 2) void k_gemm(const __half* __restrict__ Ah,
                                                 const __half* __restrict__ Wt,
                                                 const float* __restrict__ asv,
                                                 const float* __restrict__ adv) {
    int tid  = threadIdx.x;
    int w    = tid >> 5, lane = tid & 31;
    int mw   = w >> 1,  nw   = w & 1;
    int g    = lane >> 2, tg = lane & 3;
    int m0   = blockIdx.x * 128 + mw * 32;
    int n0   = nw * 64;
    int rt0  = m0 >> 4;

    float c[2][8][4];
#pragma unroll
    for (int mt = 0; mt < 2; mt++)
#pragma unroll
        for (int nt = 0; nt < 8; nt++)
#pragma unroll
            for (int q = 0; q < 4; q++) c[mt][nt][q] = 0.f;

#pragma unroll
    for (int kt = 0; kt < 8; kt++) {
        unsigned a[2][4];
#pragma unroll
        for (int mt = 0; mt < 2; mt++) {
            uint4 v = *(const uint4*)(Ah + ((((size_t)(rt0 + mt)) * 8 + kt) << 8) + (lane << 3));
            a[mt][0] = v.x; a[mt][1] = v.y; a[mt][2] = v.z; a[mt][3] = v.w;
        }
#pragma unroll
        for (int nt = 0; nt < 8; nt++) {
            uint2 vb = *(const uint2*)(Wt + ((((nw * 8 + nt) * 8) + kt) << 7) + (lane << 2));
            unsigned b[2] = {vb.x, vb.y};
            MMA16816(c[0][nt], a[0], b);
            MMA16816(c[1][nt], a[1], b);
        }
    }

    float av[16], dv[16];
#pragma unroll
    for (int nt = 0; nt < 8; nt++) {
        int col = n0 + nt * 8 + 2 * tg;
        av[2 * nt]     = asv[col];
        av[2 * nt + 1] = asv[col + 1];
        dv[2 * nt]     = adv[col];
        dv[2 * nt + 1] = adv[col + 1];
    }

#pragma unroll
    for (int mt = 0; mt < 2; mt++) {
#pragma unroll
        for (int hr = 0; hr < 2; hr++) {
            int row = m0 + mt * 16 + g + 8 * hr;
            bool ok = (row < NN);
#pragma unroll
            for (int nt = 0; nt < 8; nt++) {
                __half2 hv = __floats2half2_rn(c[mt][nt][2 * hr], c[mt][nt][2 * hr + 1]);
                if (ok)
                    *(__half2*)(g_hh + (size_t)row * NF + n0 + nt * 8 + 2 * tg) = hv;
            }
#pragma unroll
            for (int hh = 0; hh < 2; hh++) {
                float s = 0.f, t = 0.f;
#pragma unroll
                for (int q = 0; q < 4; q++) {
                    int nt = hh * 4 + q;
                    s = fmaf(c[mt][nt][2 * hr], av[2 * nt], s);
                    s = fmaf(c[mt][nt][2 * hr + 1], av[2 * nt + 1], s);
                    t = fmaf(c[mt][nt][2 * hr], dv[2 * nt], t);
                    t = fmaf(c[mt][nt][2 * hr + 1], dv[2 * nt + 1], t);
                }
                s += __shfl_xor_sync(0xffffffffu, s, 1);
                t += __shfl_xor_sync(0xffffffffu, t, 1);
                s += __shfl_xor_sync(0xffffffffu, s, 2);
                t += __shfl_xor_sync(0xffffffffu, t, 2);
                if (ok && tg == 0) {
                    int head = 2 * nw + hh;
                    g_as[row * NH + head] = s;
                    g_ad[row * NH + head] = t;
                }
            }
        }
    }
}

// ===== aggregation: warp per dst node, 2 edges/iter (half-warp each) =====
// lane = 16*half + li; li covers channels [8li, 8li+8) as one uint4; head = li>>2.

__global__ void k_agg(const float* __restrict__ bias, __half* __restrict__ xout,
                      __half* __restrict__ rm) {
    int gt = blockIdx.x * blockDim.x + threadIdx.x;
    int w = gt >> 5;
    if (w >= NN) return;
    int lane = gt & 31;
    int half = lane >> 4, li = lane & 15;
    int head = li >> 2;
    int s0 = g_rowptr[w], s1 = g_rowptr[w + 1];
    float adh = g_ad[w * NH + head];

    float acc[8];
#pragma unroll
    for (int q = 0; q < 8; q++) acc[q] = 0.f;
    float denom = 0.f;

    int nit = (s1 - s0 + 1) >> 1;              // deg >= 1 (self-loop)
    int i = s0 + half;
    int   srcC = __ldg(&g_col[min(i, s1 - 1)]);
    float vC   = (i < s1) ? 1.f : 0.f;
    uint4 rawC = __ldg((const uint4*)(g_hh + (size_t)srcC * NF + li * 8));
    float asC  = __ldg(&g_as[srcC * NH + head]);

    for (int it = 0; it < nit; it++) {
        int i2 = i + 2;
        int srcN = srcC; float vN = 0.f; uint4 rawN = rawC; float asN = asC;
        if (it + 1 < nit) {
            srcN = __ldg(&g_col[min(i2, s1 - 1)]);
            vN   = (i2 < s1) ? 1.f : 0.f;
            rawN = __ldg((const uint4*)(g_hh + (size_t)srcN * NF + li * 8));
            asN  = __ldg(&g_as[srcN * NH + head]);
        }
        float e = asC + adh;
        e = (e > 0.f) ? e : 0.2f * e;
        float wt = __expf(e) * vC;
        denom += wt;
        const __half2* hp = (const __half2*)&rawC;
#pragma unroll
        for (int q = 0; q < 4; q++) {
            float2 f = __half22float2(hp[q]);
            acc[2 * q]     = fmaf(wt, f.x, acc[2 * q]);
            acc[2 * q + 1] = fmaf(wt, f.y, acc[2 * q + 1]);
        }
        srcC = srcN; vC = vN; rawC = rawN; asC = asN;
        i = i2;
    }

    // combine halves (full-warp shfls before divergence)
    denom += __shfl_xor_sync(0xffffffffu, denom, 16);
#pragma unroll
    for (int q = 0; q < 8; q++) acc[q] += __shfl_xor_sync(0xffffffffu, acc[q], 16);

    if (half == 0) {
        float inv = 1.f / (denom + 1e-16f);
        float o[8];
        float4 b0 = *(const float4*)(bias + li * 8);
        float4 b1 = *(const float4*)(bias + li * 8 + 4);
        float bb[8] = {b0.x, b0.y, b0.z, b0.w, b1.x, b1.y, b1.z, b1.w};
#pragma unroll
        for (int q = 0; q < 8; q++) {
            float v = acc[q] * inv + bb[q];
            o[q] = (v > 0.f) ? v : expm1f(v);
        }
        __half2 hv[4];
#pragma unroll
        for (int q = 0; q < 4; q++) hv[q] = __floats2half2_rn(o[2 * q], o[2 * q + 1]);
        if (rm) {                              // final layer: row-major for pool
            *(uint4*)(rm + (size_t)w * NF + li * 8) = *(uint4*)hv;
        } else {                               // tiled for next GEMM
            int rt = w >> 4, ri = w & 15, g = ri & 7, hb = ri >> 3;
#pragma unroll
            for (int p = 0; p < 2; p++) {
                int c0 = li * 8 + p * 4;
                int kt = c0 >> 4, cc = c0 & 15, kb = cc >> 3, tg = (cc & 7) >> 1;
                size_t off = (((size_t)rt * 8 + kt) << 8) + (((g << 2) + tg) << 3)
                           + ((hb + (kb << 1)) << 1);
                *(unsigned*)(xout + off)     = *(unsigned*)&hv[2 * p];
                *(unsigned*)(xout + off + 8) = *(unsigned*)&hv[2 * p + 1];
            }
        }
    }
}

// ====================== mean pool (batch is sorted) ======================

__global__ void k_pool(const __half* __restrict__ xin, float* __restrict__ out) {
    int g = blockIdx.x, t = threadIdx.x;
    int a = g_gstart[g], b = g_gstart[g + 1];
    float s = 0.f;
    for (int n = a; n < b; n++) s += __half2float(xin[(size_t)n * NF + t]);
    out[g * NF + t] = s / fmaxf((float)(b - a), 1.f);
}

// ============================ launch ============================

extern "C" void kernel_launch(void* const* d_in, const int* in_sizes, int n_in,
                              void* d_out, int out_size) {
    const float* x   = (const float*)d_in[0];
    const float* Ws  = (const float*)d_in[1];
    const float* asv = (const float*)d_in[2];
    const float* adv = (const float*)d_in[3];
    const float* bia = (const float*)d_in[4];
    const void*  ei  = d_in[5];
    const void*  bat = d_in[6];
    float* out = (float*)d_out;

    void *p0 = nullptr, *pa = nullptr, *pb = nullptr, *pw = nullptr;
    cudaGetSymbolAddress(&p0, g_xh0);
    cudaGetSymbolAddress(&pa, g_xha);
    cudaGetSymbolAddress(&pb, g_xhb);
    cudaGetSymbolAddress(&pw, g_wt);
    __half* xh0 = (__half*)p0;
    __half* xha = (__half*)pa;
    __half* xhb = (__half*)pb;
    __half* wt  = (__half*)pw;

    k_prep    <<<1 + NBZ + NBW + NBX, 256>>>(x, Ws, ei, bat);
    k_hist    <<<NB4H, 256>>>(ei);
    k_scan_all<<<1, 1024>>>();
    k_scatgst <<<NBZ + NB4S, 256>>>(ei, bat);

    const int GB = (NN + 127) / 128;        // 391
    const int WB = (NN * 32 + 255) / 256;   // 6250

    k_gemm<<<GB, 256>>>(xh0, wt,               asv,       adv);
    k_agg <<<WB, 256>>>(bia, xha, nullptr);
    k_gemm<<<GB, 256>>>(xha, wt + NF * NF,     asv + 128, adv + 128);
    k_agg <<<WB, 256>>>(bia + NF, xhb, nullptr);
    k_gemm<<<GB, 256>>>(xhb, wt + 2 * NF * NF, asv + 256, adv + 256);
    k_agg <<<WB, 256>>>(bia + 2 * NF, nullptr, xh0);

    k_pool<<<NG, 128>>>(xh0, out);
}